// round 17
// baseline (speedup 1.0000x reference)
#include <cuda_runtime.h>
#include <cstdint>

// Problem constants
#define N_IN   16384
#define N_OUT  4096
#define THREADS 256                // 8 warps x 8 rows = 64 rows/item
#define GRID_P 148                 // persistent: one CTA per SM
#define N_ITEMS 2048               // 64 row-tiles x 4 ens x 8 K-splits(2048)
#define CHUNKS_ITEM 8              // 2048 k / 256
#define CK 256                     // k per chunk

// SMEM: A chunk [64 rows][256 k] fp32 = 64 KB x2, xw chunk [8 g2][256 k]
// float2 = 16 KB x2. Total 160 KB.
#define SM_A(b)   ((b) * 65536)
#define SM_XW(b)  (131072 + (b) * 16384)
#define SM_TOTAL  163840

// xw planes [n][g2][i] as float2 (g-pair), 0.25 mean factor folded. 4 MB.
__device__ float4 g_xwT4[(4 * 8 * N_IN) / 2];
// fp32 partials: plane p = (n*8 + ksplit) in [0,32), [p][row][g]. 8 MB.
__device__ float g_part[32 * N_OUT * 16];

union F2U { float2 f; unsigned long long u; };

__device__ __forceinline__ float2 ffma2(float2 a, float2 b, float2 c) {
    F2U A, B, C, D;
    A.f = a; B.f = b; C.f = c;
    asm("fma.rn.f32x2 %0, %1, %2, %3;"
        : "=l"(D.u) : "l"(A.u), "l"(B.u), "l"(C.u));
    return D.f;
}

__device__ __forceinline__ uint32_t smem_u32(const void* p) {
    uint32_t a;
    asm("{ .reg .u64 t; cvta.to.shared.u64 t, %1; cvt.u32.u64 %0, t; }"
        : "=r"(a) : "l"(p));
    return a;
}

__device__ __forceinline__ void cp_async16(uint32_t saddr, const void* gptr) {
    asm volatile("cp.async.cg.shared.global [%0], [%1], 16;"
                 :: "r"(saddr), "l"(gptr));
}
__device__ __forceinline__ void cp_commit() {
    asm volatile("cp.async.commit_group;");
}

// ---------------------------------------------------------------------------
// Kernel 0: xw[n][i][g] = 0.25 * sum_f x[i][f] * W[n][f][g], plane-major
// float2: g_xwT[(n*8+g2)*N_IN + i].
// ---------------------------------------------------------------------------
__global__ void precompute_xw(const float* __restrict__ x,
                              const float* __restrict__ Ws) {
    __shared__ float sW[256];
    const int n = blockIdx.y;
    sW[threadIdx.x] = Ws[n * 256 + threadIdx.x];
    __syncthreads();

    const int i = blockIdx.x * 256 + threadIdx.x;

    float xf[16];
    const float4* xv = reinterpret_cast<const float4*>(x + (size_t)i * 16);
#pragma unroll
    for (int q = 0; q < 4; ++q)
        reinterpret_cast<float4*>(xf)[q] = xv[q];

    float y[16];
#pragma unroll
    for (int g = 0; g < 16; ++g) y[g] = 0.f;
#pragma unroll
    for (int f = 0; f < 16; ++f)
#pragma unroll
        for (int g = 0; g < 16; ++g)
            y[g] += xf[f] * sW[f * 16 + g];

    float2* xwT = reinterpret_cast<float2*>(g_xwT4);
#pragma unroll
    for (int g2 = 0; g2 < 8; ++g2)
        xwT[(size_t)(n * 8 + g2) * N_IN + i] =
            make_float2(0.25f * y[2 * g2], 0.25f * y[2 * g2 + 1]);
}

// ---------------------------------------------------------------------------
// Persistent main kernel. 148 CTAs; CTA owns items cta+148j (13-14 each).
// Item = (64-row tile t, ensemble n, 2048-k split ks) -> 8 chunks of 256 k.
// R=8 rows/warp: warp w owns rows t*64 + w*8 .. +7; lane L owns k={2L,2L+1}
// within each 64-k ts-iter. ALL operands staged via cp.async (A 64 KB + xw
// 16 KB per chunk, double-buffered): no LDG in the mainloop, only 29-cyc
// conflict-free LDS (A: LDS.64, xw: LDS.128). One __syncthreads per chunk:
//   wait_group 0 ; sync ; prefetch(c+1) ; compute(c)
// acc reset at chunk 0 of item; epilogue butterfly + g_part write at chunk 7.
// ---------------------------------------------------------------------------
extern __shared__ char smem[];

__global__ void __launch_bounds__(THREADS, 1)
mfgl_main(const float* __restrict__ A) {
    const int cta  = blockIdx.x;
    const int tid  = threadIdx.x;
    const int lane = tid & 31;
    const int wid  = tid >> 5;

    const int nslots = (N_ITEMS - cta + GRID_P - 1) / GRID_P;   // 13 or 14
    const int NC = nslots * CHUNKS_ITEM;

    const float2* __restrict__ xwT = reinterpret_cast<const float2*>(g_xwT4);
    const uint32_t sbase = smem_u32(smem);

    // Prefetch chunk GC into buffer BUF. Item decode: it = cta + slot*148;
    // t = it>>5 (row tile), rem = it&31, n = rem>>3, ks = rem&7.
#define PF(GC, BUF)                                                          \
    do {                                                                     \
        const int _slot = (GC) >> 3, _cc = (GC) & 7;                         \
        const int _it = cta + _slot * GRID_P;                                \
        const int _t = _it >> 5, _rem = _it & 31;                            \
        const int _n = _rem >> 3, _ks = _rem & 7;                            \
        const int _k0 = _ks * 2048 + _cc * CK;                               \
        const float* __restrict__ _Ab =                                      \
            A + ((size_t)(_n * N_OUT + _t * 64)) * N_IN + _k0;               \
        const uint32_t _da = sbase + SM_A(BUF) + (uint32_t)tid * 16u;        \
        _Pragma("unroll")                                                    \
        for (int _i = 0; _i < 16; ++_i) {                                    \
            const int _idx = tid + _i * 256;                                 \
            cp_async16(_da + (uint32_t)_i * 4096u,                           \
                       _Ab + (size_t)(_idx >> 6) * N_IN + (_idx & 63) * 4);  \
        }                                                                    \
        const float2* __restrict__ _xb = xwT + (size_t)_n * 8 * N_IN + _k0;  \
        const uint32_t _dw = sbase + SM_XW(BUF) + (uint32_t)tid * 16u;       \
        _Pragma("unroll")                                                    \
        for (int _i = 0; _i < 4; ++_i) {                                     \
            const int _idx = tid + _i * 256;                                 \
            cp_async16(_dw + (uint32_t)_i * 4096u,                           \
                       _xb + (size_t)(_idx >> 7) * N_IN + (_idx & 127) * 2); \
        }                                                                    \
        cp_commit();                                                         \
    } while (0)

    PF(0, 0);

    float2 acc[8][8];

    for (int c = 0; c < NC; ++c) {
        const int cc = c & 7;
        const int buf = c & 1;

        if (cc == 0) {
#pragma unroll
            for (int r = 0; r < 8; ++r)
#pragma unroll
                for (int g = 0; g < 8; ++g)
                    acc[r][g] = make_float2(0.f, 0.f);
        }

        asm volatile("cp.async.wait_group 0;");  // chunk c (mine) landed
        __syncthreads();                          // all landed + WAR safe
        if (c + 1 < NC)
            PF(c + 1, buf ^ 1);                   // overlaps compute below

        const char* __restrict__ Ab = smem + SM_A(buf) + wid * (8 * 1024);
        const char* __restrict__ Wb = smem + SM_XW(buf);

#pragma unroll
        for (int ts = 0; ts < 4; ++ts) {
            // A: 8 conflict-free LDS.64 (rows of this warp)
            float2 av[8];
#pragma unroll
            for (int r = 0; r < 8; ++r)
                av[r] = *reinterpret_cast<const float2*>(
                    Ab + r * 1024 + ts * 256 + lane * 8);
            // xw: 8 conflict-free LDS.128 (one per g2 plane)
            float4 wv[8];
#pragma unroll
            for (int g2 = 0; g2 < 8; ++g2)
                wv[g2] = *reinterpret_cast<const float4*>(
                    Wb + g2 * 2048 + ts * 512 + lane * 16);

#pragma unroll
            for (int r = 0; r < 8; ++r) {
                const float2 px = make_float2(av[r].x, av[r].x);
                const float2 py = make_float2(av[r].y, av[r].y);
#pragma unroll
                for (int g2 = 0; g2 < 8; ++g2) {
                    const float2 wk0 = make_float2(wv[g2].x, wv[g2].y);
                    const float2 wk1 = make_float2(wv[g2].z, wv[g2].w);
                    acc[r][g2] = ffma2(px, wk0, acc[r][g2]);
                    acc[r][g2] = ffma2(py, wk1, acc[r][g2]);
                }
            }
        }

        if (cc == 7) {
            // item complete: butterfly-reduce the 32-lane K split, write
            // this item's g_part plane slice (deterministic, no atomics).
            const int it  = cta + (c >> 3) * GRID_P;
            const int t   = it >> 5;
            const int rem = it & 31;

#pragma unroll
            for (int r = 0; r < 8; ++r)
#pragma unroll
                for (int g = 0; g < 8; ++g) {
                    float xx = acc[r][g].x;
                    float yy = acc[r][g].y;
#pragma unroll
                    for (int off = 16; off > 0; off >>= 1) {
                        xx += __shfl_xor_sync(0xffffffffu, xx, off);
                        yy += __shfl_xor_sync(0xffffffffu, yy, off);
                    }
                    acc[r][g] = make_float2(xx, yy);
                }

            if (lane == 0) {
#pragma unroll
                for (int r = 0; r < 8; ++r) {
                    const int row = t * 64 + wid * 8 + r;
                    float2* dst = reinterpret_cast<float2*>(
                        &g_part[((size_t)rem * N_OUT + row) * 16]);
#pragma unroll
                    for (int g2 = 0; g2 < 8; ++g2)
                        dst[g2] = acc[r][g2];
                }
            }
        }
    }
}

// ---------------------------------------------------------------------------
// Reduce: out[row][g] = sum over 32 planes + mean bias. ~4 us.
// ---------------------------------------------------------------------------
__global__ void reduce_out(const float* __restrict__ bs,
                           float* __restrict__ out) {
    const int e = blockIdx.x * 256 + threadIdx.x;   // float4 idx [0, 16384)
    const int gb = (e * 4) & 15;
    float4 acc;
    acc.x = 0.25f * (bs[gb + 0] + bs[16 + gb + 0] + bs[32 + gb + 0] + bs[48 + gb + 0]);
    acc.y = 0.25f * (bs[gb + 1] + bs[16 + gb + 1] + bs[32 + gb + 1] + bs[48 + gb + 1]);
    acc.z = 0.25f * (bs[gb + 2] + bs[16 + gb + 2] + bs[32 + gb + 2] + bs[48 + gb + 2]);
    acc.w = 0.25f * (bs[gb + 3] + bs[16 + gb + 3] + bs[32 + gb + 3] + bs[48 + gb + 3]);
    const float4* gp = reinterpret_cast<const float4*>(g_part);
#pragma unroll
    for (int p = 0; p < 32; ++p) {
        const float4 v = gp[(size_t)p * 16384 + e];
        acc.x += v.x; acc.y += v.y; acc.z += v.z; acc.w += v.w;
    }
    reinterpret_cast<float4*>(out)[e] = acc;
}

// ---------------------------------------------------------------------------
// Launch: inputs in metadata order: x, As, Ws, bs. Output fp32 [4096,16].
// ---------------------------------------------------------------------------
extern "C" void kernel_launch(void* const* d_in, const int* in_sizes, int n_in,
                              void* d_out, int out_size) {
    const float* x  = (const float*)d_in[0];
    const float* As = (const float*)d_in[1];
    const float* Ws = (const float*)d_in[2];
    const float* bs = (const float*)d_in[3];
    float* out = (float*)d_out;

    precompute_xw<<<dim3(N_IN / 256, 4), 256>>>(x, Ws);

    cudaFuncSetAttribute(mfgl_main,
                         cudaFuncAttributeMaxDynamicSharedMemorySize,
                         SM_TOTAL);
    mfgl_main<<<GRID_P, THREADS, SM_TOTAL>>>(As);

    reduce_out<<<16384 / 256, 256>>>(bs, out);
}